// round 5
// baseline (speedup 1.0000x reference)
#include <cuda_runtime.h>
#include <cstdint>
#include <math.h>

#define BB 2
#define SS 2048
#define DIM 1536
#define NH 12
#define HD 128
#define SIGMA 12
#define M_TOT (BB * SS)      // 4096
#define N_QKV (3 * DIM)      // 4608

// ---------------- scratch (__device__ globals; allocation-free rule) -------
// All GEMM A/B operands live in "chunk-permuted" layout: within each 16-col
// group, col (t + 4j) is stored at position (t*4 + j). This makes one 16B
// chunk hold exactly the m16n8k8 fragment quad for two k-steps.
__device__ float g_x[(size_t)M_TOT * DIM];        // permuted, tf32-rounded x
__device__ float g_wqkvT[(size_t)N_QKV * DIM];    // permuted Wqkv^T
__device__ float g_woutT[(size_t)DIM * DIM];      // permuted Wout^T
__device__ float g_qkv[(size_t)M_TOT * N_QKV];    // QKV output (standard)
__device__ float g_att[(size_t)M_TOT * DIM];      // attention out (permuted)

// ---------------- helpers ---------------------------------------------------
__device__ __forceinline__ uint32_t smem_u32(const void* p) {
    uint32_t a;
    asm("{ .reg .u64 t; cvta.to.shared.u64 t, %1; cvt.u32.u64 %0, t; }"
        : "=r"(a) : "l"(p));
    return a;
}
__device__ __forceinline__ float rna_tf32(float x) {
    uint32_t r;
    asm("cvt.rna.tf32.f32 %0, %1;" : "=r"(r) : "f"(x));
    return __uint_as_float(r);
}
__device__ __forceinline__ void cp16(uint32_t dst, const void* src) {
    asm volatile("cp.async.cg.shared.global [%0], [%1], 16;"
                 :: "r"(dst), "l"(src) : "memory");
}
__device__ __forceinline__ void cp_commit() {
    asm volatile("cp.async.commit_group;" ::: "memory");
}
template <int N>
__device__ __forceinline__ void cp_wait() {
    asm volatile("cp.async.wait_group %0;" :: "n"(N) : "memory");
}
__device__ __forceinline__ void mma_tf32(float* c,
                                         uint32_t a0, uint32_t a1, uint32_t a2, uint32_t a3,
                                         uint32_t b0, uint32_t b1) {
    asm volatile(
        "mma.sync.aligned.m16n8k8.row.col.f32.tf32.tf32.f32 "
        "{%0,%1,%2,%3}, {%4,%5,%6,%7}, {%8,%9}, {%0,%1,%2,%3};"
        : "+f"(c[0]), "+f"(c[1]), "+f"(c[2]), "+f"(c[3])
        : "r"(a0), "r"(a1), "r"(a2), "r"(a3), "r"(b0), "r"(b1));
}
#define FU(x) __float_as_uint(x)

// ---------------- tf32 GEMM: CTA 128(B N) x BMT, 4 warps of (BMT/2)x64 ------
// A:[M,K] permuted row-major, BT:[N,K] permuted row-major, C standard.
#define BN 128
#define BKF 32
#define STAGES 3

template <int BMT>
__global__ __launch_bounds__(128, 2)
void gemm_tf32_mma(const float* __restrict__ A, const float* __restrict__ BT,
                   const float* __restrict__ bias, float* __restrict__ C,
                   int Ndim, int K) {
    constexpr int MT = BMT / 32;          // m16 tiles per warp
    constexpr int A_ST = BMT * 128;       // bytes per A stage
    constexpr int B_ST = BN * 128;
    constexpr int STG = A_ST + B_ST;
    extern __shared__ char smem[];
    const uint32_t sbase = smem_u32(smem);

    const int tid = threadIdx.x;
    const int wid = tid >> 5;
    const int lane = tid & 31;
    const int g = lane >> 2;              // 0..7
    const int t = lane & 3;               // 0..3
    const int warp_m = wid >> 1;          // 0..1
    const int warp_n = wid & 1;           // 0..1
    const int m0 = blockIdx.y * BMT;
    const int n0 = blockIdx.x * BN;
    const int KT = K / BKF;

    const int lc = tid & 7;               // loader chunk
    const int lr = tid >> 3;              // loader row base (0..15)

    auto load_stage = [&](int stage, int kt) {
        const float* Ak = A + (size_t)m0 * K + kt * BKF;
        const float* Bk = BT + (size_t)n0 * K + kt * BKF;
        const uint32_t sA = sbase + stage * STG;
        const uint32_t sB = sA + A_ST;
#pragma unroll
        for (int i = 0; i < BMT / 16; i++) {
            int row = i * 16 + lr;
            cp16(sA + row * 128 + (((lc + ((row & 1) << 2)) & 7) << 4),
                 Ak + (size_t)row * K + lc * 4);
        }
#pragma unroll
        for (int i = 0; i < BN / 16; i++) {
            int row = i * 16 + lr;
            cp16(sB + row * 128 + (((lc + ((row & 1) << 2)) & 7) << 4),
                 Bk + (size_t)row * K + lc * 4);
        }
        cp_commit();
    };

    float acc[MT][8][4];
#pragma unroll
    for (int i = 0; i < MT; i++)
#pragma unroll
        for (int j = 0; j < 8; j++)
#pragma unroll
            for (int r = 0; r < 4; r++) acc[i][j][r] = 0.0f;

    load_stage(0, 0);
    load_stage(1, 1);

    for (int kt = 0; kt < KT; ++kt) {
        cp_wait<1>();
        __syncthreads();
        if (kt + 2 < KT) load_stage((kt + 2) % STAGES, kt + 2);

        const char* sA = smem + (kt % STAGES) * STG;
        const char* sB = sA + A_ST;

#pragma unroll
        for (int h = 0; h < 2; h++) {
            float4 av[MT][2];
#pragma unroll
            for (int mt = 0; mt < MT; mt++)
#pragma unroll
                for (int rr = 0; rr < 2; rr++) {
                    int row = warp_m * (BMT / 2) + mt * 16 + rr * 8 + g;
                    int ch = ((h * 4 + t) + ((row & 1) << 2)) & 7;
                    av[mt][rr] = *(const float4*)(sA + row * 128 + ch * 16);
                }
            float4 bv[8];
#pragma unroll
            for (int nt = 0; nt < 8; nt++) {
                int row = warp_n * 64 + nt * 8 + g;
                int ch = ((h * 4 + t) + ((row & 1) << 2)) & 7;
                bv[nt] = *(const float4*)(sB + row * 128 + ch * 16);
            }
#pragma unroll
            for (int mt = 0; mt < MT; mt++) {
#pragma unroll
                for (int nt = 0; nt < 8; nt++) {
                    mma_tf32(acc[mt][nt],
                             FU(av[mt][0].x), FU(av[mt][1].x),
                             FU(av[mt][0].y), FU(av[mt][1].y),
                             FU(bv[nt].x), FU(bv[nt].y));
                    mma_tf32(acc[mt][nt],
                             FU(av[mt][0].z), FU(av[mt][1].z),
                             FU(av[mt][0].w), FU(av[mt][1].w),
                             FU(bv[nt].z), FU(bv[nt].w));
                }
            }
        }
    }

    // epilogue
#pragma unroll
    for (int mt = 0; mt < MT; mt++) {
        const int r0 = m0 + warp_m * (BMT / 2) + mt * 16 + g;
#pragma unroll
        for (int nt = 0; nt < 8; nt++) {
            const int col = n0 + warp_n * 64 + nt * 8 + 2 * t;
            const float2 bv = *reinterpret_cast<const float2*>(bias + col);
            float2 o0, o1;
            o0.x = acc[mt][nt][0] + bv.x;
            o0.y = acc[mt][nt][1] + bv.y;
            o1.x = acc[mt][nt][2] + bv.x;
            o1.y = acc[mt][nt][3] + bv.y;
            *reinterpret_cast<float2*>(C + (size_t)r0 * Ndim + col) = o0;
            *reinterpret_cast<float2*>(C + (size_t)(r0 + 8) * Ndim + col) = o1;
        }
    }
}

// ---------------- pre-pass kernels (write permuted layouts) -----------------
// out chunk q holds cols {16*grp + t + 4j}, rounded to tf32.
__global__ __launch_bounds__(256)
void round_x_perm(const float* __restrict__ in, float* __restrict__ out) {
    int q = blockIdx.x * blockDim.x + threadIdx.x;   // chunk id
    if (q >= M_TOT * DIM / 4) return;
    int r = q / (DIM / 4);
    int cq = q % (DIM / 4);
    int grp = cq >> 2, t = cq & 3;
    const float* src = in + (size_t)r * DIM + grp * 16 + t;
    float4 o;
    o.x = rna_tf32(src[0]);
    o.y = rna_tf32(src[4]);
    o.z = rna_tf32(src[8]);
    o.w = rna_tf32(src[12]);
    reinterpret_cast<float4*>(out)[q] = o;
}

// in: R x C row-major; out: C x R row-major, tf32-rounded, chunk-permuted cols
__global__ __launch_bounds__(1024)
void transpose_rna_perm(const float* __restrict__ in, float* __restrict__ out,
                        int R, int C) {
    __shared__ float tbuf[32][33];
    int c = blockIdx.x * 32 + threadIdx.x;
    int r = blockIdx.y * 32 + threadIdx.y;
    tbuf[threadIdx.y][threadIdx.x] = in[(size_t)r * C + c];
    __syncthreads();
    int oc = blockIdx.y * 32 + threadIdx.x;          // index along R (K dim)
    int orow = blockIdx.x * 32 + threadIdx.y;        // index along C (N dim)
    int poc = (oc & ~15) | ((oc & 3) << 2) | ((oc >> 2) & 3);
    out[(size_t)orow * R + poc] = rna_tf32(tbuf[threadIdx.x][threadIdx.y]);
}

// ---------------- anchor attention (one warp per (b,h,s)) -------------------
// q,k read contiguous; v accumulated per permuted chunk so g_att is written
// directly in the GEMM2-A permuted layout.
__global__ __launch_bounds__(256)
void anchor_attn_kernel(const float* __restrict__ gs) {
    const int gw = (blockIdx.x * blockDim.x + threadIdx.x) >> 5;
    const int lane = threadIdx.x & 31;

    const int s = gw % SS;
    const int h = (gw / SS) % NH;
    const int b = gw / (SS * NH);

    const float g0 = gs[0], g1 = gs[1], g2 = gs[2];
    const float mx = fmaxf(g0, fmaxf(g1, g2));
    const float lse = mx + logf(expf(g0 - mx) + expf(g1 - mx) + expf(g2 - mx));
    const float lw0 = g0 - lse, lw1 = g1 - lse, lw2 = g2 - lse;

    const float* base = g_qkv + (size_t)b * SS * N_QKV;
    const int hc = h * HD + lane * 4;

    const float4 q = *reinterpret_cast<const float4*>(base + (size_t)s * N_QKV + hc);

    int aidx[SIGMA];
    const int offs[10] = {-3, -2, -1, 1, 2, 3, -10, -5, 5, 10};
#pragma unroll
    for (int a = 0; a < 10; a++) {
        int j = s + offs[a];
        aidx[a] = j < 0 ? 0 : (j > SS - 1 ? SS - 1 : j);
    }
    aidx[10] = 0;
    aidx[11] = SS - 1;

    const float scale = 0.08838834764831845f;
    float sc[SIGMA];
#pragma unroll
    for (int a = 0; a < SIGMA; a++) {
        const float4 kv = *reinterpret_cast<const float4*>(
            base + (size_t)aidx[a] * N_QKV + DIM + hc);
        float d = q.x * kv.x + q.y * kv.y + q.z * kv.z + q.w * kv.w;
#pragma unroll
        for (int o = 16; o > 0; o >>= 1)
            d += __shfl_xor_sync(0xffffffffu, d, o);
        const float lw = (a < 6) ? lw0 : ((a < 10) ? lw1 : lw2);
        sc[a] = d * scale + lw;
    }

    float m = sc[0];
#pragma unroll
    for (int a = 1; a < SIGMA; a++) m = fmaxf(m, sc[a]);
    float sum = 0.0f;
#pragma unroll
    for (int a = 0; a < SIGMA; a++) { sc[a] = __expf(sc[a] - m); sum += sc[a]; }
    const float inv = 1.0f / sum;

    // permuted-chunk dims this lane owns: 16*(lane>>2) + (lane&3) + 4j
    const int vdim = h * HD + 16 * (lane >> 2) + (lane & 3);
    float4 acc = make_float4(0.f, 0.f, 0.f, 0.f);
#pragma unroll
    for (int a = 0; a < SIGMA; a++) {
        const float w = sc[a] * inv;
        const float* vr = base + (size_t)aidx[a] * N_QKV + 2 * DIM + vdim;
        acc.x += w * vr[0];
        acc.y += w * vr[4];
        acc.z += w * vr[8];
        acc.w += w * vr[12];
    }
    acc.x = rna_tf32(acc.x); acc.y = rna_tf32(acc.y);
    acc.z = rna_tf32(acc.z); acc.w = rna_tf32(acc.w);

    *reinterpret_cast<float4*>(
        g_att + (size_t)(b * SS + s) * DIM + hc) = acc;
}

// ---------------------------------------------------------------------------
extern "C" void kernel_launch(void* const* d_in, const int* in_sizes, int n_in,
                              void* d_out, int out_size) {
    const float* x    = (const float*)d_in[0];
    const float* Wqkv = (const float*)d_in[1];
    const float* bqkv = (const float*)d_in[2];
    const float* Wout = (const float*)d_in[3];
    const float* bout = (const float*)d_in[4];
    const float* gsc  = (const float*)d_in[5];
    float* out = (float*)d_out;

    float *px, *pwqkvT, *pwoutT, *pqkv, *patt;
    cudaGetSymbolAddress((void**)&px, g_x);
    cudaGetSymbolAddress((void**)&pwqkvT, g_wqkvT);
    cudaGetSymbolAddress((void**)&pwoutT, g_woutT);
    cudaGetSymbolAddress((void**)&pqkv, g_qkv);
    cudaGetSymbolAddress((void**)&patt, g_att);

    constexpr int SM128 = STAGES * (128 * 128 + BN * 128);  // 98304
    constexpr int SM64  = STAGES * (64 * 128 + BN * 128);   // 73728

    static bool attr_set = false;
    if (!attr_set) {
        cudaFuncSetAttribute(gemm_tf32_mma<128>,
                             cudaFuncAttributeMaxDynamicSharedMemorySize, SM128);
        cudaFuncSetAttribute(gemm_tf32_mma<64>,
                             cudaFuncAttributeMaxDynamicSharedMemorySize, SM64);
        attr_set = true;
    }

    // 1) round + permute x
    round_x_perm<<<(M_TOT * DIM / 4 + 255) / 256, 256>>>(x, px);
    // 2) transpose + round + permute weights
    transpose_rna_perm<<<dim3(N_QKV / 32, DIM / 32), dim3(32, 32)>>>(Wqkv, pwqkvT, DIM, N_QKV);
    transpose_rna_perm<<<dim3(DIM / 32, DIM / 32), dim3(32, 32)>>>(Wout, pwoutT, DIM, DIM);

    // 3) QKV projection: (4096x1536) @ (1536x4608)
    gemm_tf32_mma<128><<<dim3(N_QKV / BN, M_TOT / 128), 128, SM128>>>(
        px, pwqkvT, bqkv, pqkv, N_QKV, DIM);

    // 4) anchor attention
    anchor_attn_kernel<<<BB * NH * SS * 32 / 256, 256>>>(gsc);

    // 5) output projection: (4096x1536) @ (1536x1536)
    gemm_tf32_mma<64><<<dim3(DIM / BN, M_TOT / 64), 128, SM64>>>(
        patt, pwoutT, bout, out, DIM, DIM);
}

// round 6
// speedup vs baseline: 1.7012x; 1.7012x over previous
#include <cuda_runtime.h>
#include <cuda_fp16.h>
#include <cstdint>
#include <math.h>

#define BB 2
#define SS 2048
#define DIM 1536
#define NH 12
#define HD 128
#define SIGMA 12
#define M_TOT (BB * SS)      // 4096
#define N_QKV (3 * DIM)      // 4608

// ---------------- scratch (__device__ globals; allocation-free rule) -------
// GEMM A/B operands are fp16 in "chunk-permuted" layout: within each 32-col
// group, chunk t (8 halves) = cols {2t,2t+1,8+2t,9+2t,16+2t,17+2t,24+2t,25+2t}.
// One 16B chunk per row = the m16n8k16 fragment halves for two k16 steps.
__device__ __half g_xh[(size_t)M_TOT * DIM];       // permuted x
__device__ __half g_wqkvT[(size_t)N_QKV * DIM];    // permuted Wqkv^T
__device__ __half g_woutT[(size_t)DIM * DIM];      // permuted Wout^T
__device__ float  g_qkv[(size_t)M_TOT * N_QKV];    // QKV output (fp32, standard)
__device__ __half g_att[(size_t)M_TOT * DIM];      // attention out (permuted)

// ---------------- helpers ---------------------------------------------------
__device__ __forceinline__ uint32_t smem_u32(const void* p) {
    uint32_t a;
    asm("{ .reg .u64 t; cvta.to.shared.u64 t, %1; cvt.u32.u64 %0, t; }"
        : "=r"(a) : "l"(p));
    return a;
}
__device__ __forceinline__ void cp16(uint32_t dst, const void* src) {
    asm volatile("cp.async.cg.shared.global [%0], [%1], 16;"
                 :: "r"(dst), "l"(src) : "memory");
}
__device__ __forceinline__ void cp_commit() {
    asm volatile("cp.async.commit_group;" ::: "memory");
}
template <int N>
__device__ __forceinline__ void cp_wait() {
    asm volatile("cp.async.wait_group %0;" :: "n"(N) : "memory");
}
__device__ __forceinline__ void mma_f16(float* c,
                                        uint32_t a0, uint32_t a1, uint32_t a2, uint32_t a3,
                                        uint32_t b0, uint32_t b1) {
    asm volatile(
        "mma.sync.aligned.m16n8k16.row.col.f32.f16.f16.f32 "
        "{%0,%1,%2,%3}, {%4,%5,%6,%7}, {%8,%9}, {%0,%1,%2,%3};"
        : "+f"(c[0]), "+f"(c[1]), "+f"(c[2]), "+f"(c[3])
        : "r"(a0), "r"(a1), "r"(a2), "r"(a3), "r"(b0), "r"(b1));
}
#define F4U(v, i) (reinterpret_cast<const uint32_t*>(&(v))[i])

// ---------------- fp16 GEMM: CTA BN(128) x BMT, 4 warps of (BMT/2)x64 -------
// A:[M,K] permuted halves, BT:[N,K] permuted halves, C fp32 standard.
#define BN 128
#define BKH 64               // halves per k-iter (128B rows)
#define STAGES 3

template <int BMT>
__global__ __launch_bounds__(128, 2)
void gemm_f16_mma(const __half* __restrict__ A, const __half* __restrict__ BT,
                  const float* __restrict__ bias, float* __restrict__ C,
                  int Ndim, int K) {
    constexpr int MT = BMT / 32;          // m16 tiles per warp
    constexpr int A_ST = BMT * 128;       // bytes per A stage
    constexpr int B_ST = BN * 128;
    constexpr int STG = A_ST + B_ST;
    extern __shared__ char smem[];
    const uint32_t sbase = smem_u32(smem);

    const int tid = threadIdx.x;
    const int wid = tid >> 5;
    const int lane = tid & 31;
    const int g = lane >> 2;              // 0..7
    const int t = lane & 3;               // 0..3
    const int warp_m = wid >> 1;          // 0..1
    const int warp_n = wid & 1;           // 0..1
    const int m0 = blockIdx.y * BMT;
    const int n0 = blockIdx.x * BN;
    const int KT = K / BKH;

    const int lc = tid & 7;               // loader chunk
    const int lr = tid >> 3;              // loader row base (0..15)

    auto load_stage = [&](int stage, int kt) {
        const __half* Ak = A + (size_t)m0 * K + kt * BKH;
        const __half* Bk = BT + (size_t)n0 * K + kt * BKH;
        const uint32_t sA = sbase + stage * STG;
        const uint32_t sB = sA + A_ST;
#pragma unroll
        for (int i = 0; i < BMT / 16; i++) {
            int row = i * 16 + lr;
            cp16(sA + row * 128 + (((lc + ((row & 1) << 2)) & 7) << 4),
                 Ak + (size_t)row * K + lc * 8);
        }
#pragma unroll
        for (int i = 0; i < BN / 16; i++) {
            int row = i * 16 + lr;
            cp16(sB + row * 128 + (((lc + ((row & 1) << 2)) & 7) << 4),
                 Bk + (size_t)row * K + lc * 8);
        }
        cp_commit();
    };

    float acc[MT][8][4];
#pragma unroll
    for (int i = 0; i < MT; i++)
#pragma unroll
        for (int j = 0; j < 8; j++)
#pragma unroll
            for (int r = 0; r < 4; r++) acc[i][j][r] = 0.0f;

    load_stage(0, 0);
    load_stage(1, 1);

    const int gp = g & 1;                 // row parity for all fragment rows

    for (int kt = 0; kt < KT; ++kt) {
        cp_wait<1>();
        __syncthreads();
        if (kt + 2 < KT) load_stage((kt + 2) % STAGES, kt + 2);

        const char* sA = smem + (kt % STAGES) * STG;
        const char* sB = sA + A_ST;

#pragma unroll
        for (int h = 0; h < 2; h++) {
            const int ch = t + ((h ^ gp) << 2);   // swizzled chunk, 0..7
            float4 av[MT][2];
#pragma unroll
            for (int mt = 0; mt < MT; mt++)
#pragma unroll
                for (int rr = 0; rr < 2; rr++) {
                    int row = warp_m * (BMT / 2) + mt * 16 + rr * 8 + g;
                    av[mt][rr] = *(const float4*)(sA + row * 128 + ch * 16);
                }
            float4 bv[8];
#pragma unroll
            for (int nt = 0; nt < 8; nt++) {
                int row = warp_n * 64 + nt * 8 + g;
                bv[nt] = *(const float4*)(sB + row * 128 + ch * 16);
            }
#pragma unroll
            for (int mt = 0; mt < MT; mt++) {
#pragma unroll
                for (int nt = 0; nt < 8; nt++) {
                    // k16 step 0 of this chunk
                    mma_f16(acc[mt][nt],
                            F4U(av[mt][0], 0), F4U(av[mt][1], 0),
                            F4U(av[mt][0], 1), F4U(av[mt][1], 1),
                            F4U(bv[nt], 0), F4U(bv[nt], 1));
                    // k16 step 1 of this chunk
                    mma_f16(acc[mt][nt],
                            F4U(av[mt][0], 2), F4U(av[mt][1], 2),
                            F4U(av[mt][0], 3), F4U(av[mt][1], 3),
                            F4U(bv[nt], 2), F4U(bv[nt], 3));
                }
            }
        }
    }

    // epilogue (fp32 + bias)
#pragma unroll
    for (int mt = 0; mt < MT; mt++) {
        const int r0 = m0 + warp_m * (BMT / 2) + mt * 16 + g;
#pragma unroll
        for (int nt = 0; nt < 8; nt++) {
            const int col = n0 + warp_n * 64 + nt * 8 + 2 * t;
            const float2 bv = *reinterpret_cast<const float2*>(bias + col);
            float2 o0, o1;
            o0.x = acc[mt][nt][0] + bv.x;
            o0.y = acc[mt][nt][1] + bv.y;
            o1.x = acc[mt][nt][2] + bv.x;
            o1.y = acc[mt][nt][3] + bv.y;
            *reinterpret_cast<float2*>(C + (size_t)r0 * Ndim + col) = o0;
            *reinterpret_cast<float2*>(C + (size_t)(r0 + 8) * Ndim + col) = o1;
        }
    }
}

// ---------------- pre-pass kernels (write permuted fp16 layouts) ------------
// One thread per 16B output chunk (8 halves).
__global__ __launch_bounds__(256)
void x_to_half_perm(const float* __restrict__ in, __half* __restrict__ out) {
    int q = blockIdx.x * blockDim.x + threadIdx.x;
    if (q >= M_TOT * DIM / 8) return;
    int r = q / (DIM / 8);
    int c = q % (DIM / 8);
    int grp = c >> 2, t = c & 3;
    const float* src = in + (size_t)r * DIM + grp * 32 + 2 * t;
    __half2 h0 = __floats2half2_rn(src[0], src[1]);
    __half2 h1 = __floats2half2_rn(src[8], src[9]);
    __half2 h2 = __floats2half2_rn(src[16], src[17]);
    __half2 h3 = __floats2half2_rn(src[24], src[25]);
    uint4 o;
    o.x = *reinterpret_cast<uint32_t*>(&h0);
    o.y = *reinterpret_cast<uint32_t*>(&h1);
    o.z = *reinterpret_cast<uint32_t*>(&h2);
    o.w = *reinterpret_cast<uint32_t*>(&h3);
    reinterpret_cast<uint4*>(out)[q] = o;
}

// in: R x C row-major fp32; out: C x R halves, chunk-permuted along R(=K)
__global__ __launch_bounds__(1024)
void transpose_half_perm(const float* __restrict__ in, __half* __restrict__ out,
                         int R, int C) {
    __shared__ float tbuf[32][33];
    int c = blockIdx.x * 32 + threadIdx.x;
    int r = blockIdx.y * 32 + threadIdx.y;
    tbuf[threadIdx.y][threadIdx.x] = in[(size_t)r * C + c];
    __syncthreads();
    int oc = blockIdx.y * 32 + threadIdx.x;     // K index
    int orow = blockIdx.x * 32 + threadIdx.y;   // N index
    int w = oc & 31;
    int ppos = (oc & ~31) | (((w >> 1) & 3) << 3) | ((w >> 3) << 1) | (w & 1);
    out[(size_t)orow * R + ppos] = __float2half_rn(tbuf[threadIdx.x][threadIdx.y]);
}

// ---------------- anchor attention (one warp per (b,h,s)) -------------------
__global__ __launch_bounds__(256)
void anchor_attn_kernel(const float* __restrict__ gs) {
    const int gw = (blockIdx.x * blockDim.x + threadIdx.x) >> 5;
    const int lane = threadIdx.x & 31;

    const int s = gw % SS;
    const int h = (gw / SS) % NH;
    const int b = gw / (SS * NH);

    const float g0 = gs[0], g1 = gs[1], g2 = gs[2];
    const float mx = fmaxf(g0, fmaxf(g1, g2));
    const float lse = mx + logf(expf(g0 - mx) + expf(g1 - mx) + expf(g2 - mx));
    const float lw0 = g0 - lse, lw1 = g1 - lse, lw2 = g2 - lse;

    const float* base = g_qkv + (size_t)b * SS * N_QKV;
    const int hc = h * HD + lane * 4;

    const float4 q = *reinterpret_cast<const float4*>(base + (size_t)s * N_QKV + hc);

    int aidx[SIGMA];
    const int offs[10] = {-3, -2, -1, 1, 2, 3, -10, -5, 5, 10};
#pragma unroll
    for (int a = 0; a < 10; a++) {
        int j = s + offs[a];
        aidx[a] = j < 0 ? 0 : (j > SS - 1 ? SS - 1 : j);
    }
    aidx[10] = 0;
    aidx[11] = SS - 1;

    const float scale = 0.08838834764831845f;
    float sc[SIGMA];
#pragma unroll
    for (int a = 0; a < SIGMA; a++) {
        const float4 kv = *reinterpret_cast<const float4*>(
            base + (size_t)aidx[a] * N_QKV + DIM + hc);
        float d = q.x * kv.x + q.y * kv.y + q.z * kv.z + q.w * kv.w;
#pragma unroll
        for (int o = 16; o > 0; o >>= 1)
            d += __shfl_xor_sync(0xffffffffu, d, o);
        const float lw = (a < 6) ? lw0 : ((a < 10) ? lw1 : lw2);
        sc[a] = d * scale + lw;
    }

    float m = sc[0];
#pragma unroll
    for (int a = 1; a < SIGMA; a++) m = fmaxf(m, sc[a]);
    float sum = 0.0f;
#pragma unroll
    for (int a = 0; a < SIGMA; a++) { sc[a] = __expf(sc[a] - m); sum += sc[a]; }
    const float inv = 1.0f / sum;

    // permuted-chunk dims this lane owns:
    // chunk c = lane>>1 (within head), halfsel = lane&1
    // dims = G*32 + 16*halfsel + 2t + {0,1,8,9}, G = c>>2, t = c&3
    const int cch = lane >> 1;
    const int hs = lane & 1;
    const int d0 = h * HD + (cch >> 2) * 32 + hs * 16 + 2 * (cch & 3);
    float4 acc = make_float4(0.f, 0.f, 0.f, 0.f);
#pragma unroll
    for (int a = 0; a < SIGMA; a++) {
        const float w = sc[a] * inv;
        const float* vr = base + (size_t)aidx[a] * N_QKV + 2 * DIM + d0;
        const float2 v0 = *reinterpret_cast<const float2*>(vr);
        const float2 v1 = *reinterpret_cast<const float2*>(vr + 8);
        acc.x += w * v0.x; acc.y += w * v0.y;
        acc.z += w * v1.x; acc.w += w * v1.y;
    }

    __half2 p0 = __floats2half2_rn(acc.x, acc.y);
    __half2 p1 = __floats2half2_rn(acc.z, acc.w);
    uint2 o;
    o.x = *reinterpret_cast<uint32_t*>(&p0);
    o.y = *reinterpret_cast<uint32_t*>(&p1);
    *reinterpret_cast<uint2*>(
        g_att + (size_t)(b * SS + s) * DIM + h * HD + cch * 8 + hs * 4) = o;
}

// ---------------------------------------------------------------------------
extern "C" void kernel_launch(void* const* d_in, const int* in_sizes, int n_in,
                              void* d_out, int out_size) {
    const float* x    = (const float*)d_in[0];
    const float* Wqkv = (const float*)d_in[1];
    const float* bqkv = (const float*)d_in[2];
    const float* Wout = (const float*)d_in[3];
    const float* bout = (const float*)d_in[4];
    const float* gsc  = (const float*)d_in[5];
    float* out = (float*)d_out;

    __half *pxh, *pwqkvT, *pwoutT, *patt;
    float *pqkv;
    cudaGetSymbolAddress((void**)&pxh, g_xh);
    cudaGetSymbolAddress((void**)&pwqkvT, g_wqkvT);
    cudaGetSymbolAddress((void**)&pwoutT, g_woutT);
    cudaGetSymbolAddress((void**)&pqkv, g_qkv);
    cudaGetSymbolAddress((void**)&patt, g_att);

    constexpr int SM128 = STAGES * (128 * 128 + BN * 128);  // 98304
    constexpr int SM64  = STAGES * (64 * 128 + BN * 128);   // 73728

    static bool attr_set = false;
    if (!attr_set) {
        cudaFuncSetAttribute(gemm_f16_mma<128>,
                             cudaFuncAttributeMaxDynamicSharedMemorySize, SM128);
        cudaFuncSetAttribute(gemm_f16_mma<64>,
                             cudaFuncAttributeMaxDynamicSharedMemorySize, SM64);
        attr_set = true;
    }

    // 1) x -> permuted fp16
    x_to_half_perm<<<(M_TOT * DIM / 8 + 255) / 256, 256>>>(x, pxh);
    // 2) transpose + permute weights -> fp16
    transpose_half_perm<<<dim3(N_QKV / 32, DIM / 32), dim3(32, 32)>>>(Wqkv, pwqkvT, DIM, N_QKV);
    transpose_half_perm<<<dim3(DIM / 32, DIM / 32), dim3(32, 32)>>>(Wout, pwoutT, DIM, DIM);

    // 3) QKV projection: (4096x1536) @ (1536x4608)
    gemm_f16_mma<128><<<dim3(N_QKV / BN, M_TOT / 128), 128, SM128>>>(
        pxh, pwqkvT, bqkv, pqkv, N_QKV, DIM);

    // 4) anchor attention
    anchor_attn_kernel<<<BB * NH * SS * 32 / 256, 256>>>(gsc);

    // 5) output projection: (4096x1536) @ (1536x1536)
    gemm_f16_mma<64><<<dim3(DIM / BN, M_TOT / 64), 128, SM64>>>(
        patt, pwoutT, bout, out, DIM, DIM);
}

// round 7
// speedup vs baseline: 1.7413x; 1.0236x over previous
#include <cuda_runtime.h>
#include <cuda_fp16.h>
#include <cstdint>
#include <math.h>

#define BB 2
#define SS 2048
#define DIM 1536
#define NH 12
#define HD 128
#define SIGMA 12
#define M_TOT (BB * SS)      // 4096
#define N_QKV (3 * DIM)      // 4608

// ---------------- scratch (__device__ globals; allocation-free rule) -------
// GEMM A/B operands are fp16 in "chunk-permuted" layout: within each 32-col
// group, chunk t (8 halves) = cols {2t,2t+1,8+2t,9+2t,16+2t,17+2t,24+2t,25+2t}.
__device__ __half g_xh[(size_t)M_TOT * DIM];       // permuted x
__device__ __half g_wqkvT[(size_t)N_QKV * DIM];    // permuted Wqkv^T
__device__ __half g_woutT[(size_t)DIM * DIM];      // permuted Wout^T
__device__ __half g_qkvh[(size_t)M_TOT * N_QKV];   // QKV output (fp16, standard)
__device__ __half g_att[(size_t)M_TOT * DIM];      // attention out (permuted)

// ---------------- helpers ---------------------------------------------------
__device__ __forceinline__ uint32_t smem_u32(const void* p) {
    uint32_t a;
    asm("{ .reg .u64 t; cvta.to.shared.u64 t, %1; cvt.u32.u64 %0, t; }"
        : "=r"(a) : "l"(p));
    return a;
}
__device__ __forceinline__ void cp16(uint32_t dst, const void* src) {
    asm volatile("cp.async.cg.shared.global [%0], [%1], 16;"
                 :: "r"(dst), "l"(src) : "memory");
}
__device__ __forceinline__ void cp_commit() {
    asm volatile("cp.async.commit_group;" ::: "memory");
}
template <int N>
__device__ __forceinline__ void cp_wait() {
    asm volatile("cp.async.wait_group %0;" :: "n"(N) : "memory");
}
__device__ __forceinline__ void mma_f16(float* c,
                                        uint32_t a0, uint32_t a1, uint32_t a2, uint32_t a3,
                                        uint32_t b0, uint32_t b1) {
    asm volatile(
        "mma.sync.aligned.m16n8k16.row.col.f32.f16.f16.f32 "
        "{%0,%1,%2,%3}, {%4,%5,%6,%7}, {%8,%9}, {%0,%1,%2,%3};"
        : "+f"(c[0]), "+f"(c[1]), "+f"(c[2]), "+f"(c[3])
        : "r"(a0), "r"(a1), "r"(a2), "r"(a3), "r"(b0), "r"(b1));
}
#define F4U(v, i) (reinterpret_cast<const uint32_t*>(&(v))[i])

// ---------------- fp16 GEMM: CTA BN(128) x BMT, 4 warps of (BMT/2)x64 -------
// A:[M,K] permuted halves, BT:[N,K] permuted halves, C standard (OutT).
#define BN 128
#define BKH 64               // halves per k-iter (128B rows)
#define STAGES 3

template <int BMT, typename OutT>
__global__ __launch_bounds__(128, 2)
void gemm_f16_mma(const __half* __restrict__ A, const __half* __restrict__ BT,
                  const float* __restrict__ bias, OutT* __restrict__ C,
                  int Ndim, int K) {
    constexpr int MT = BMT / 32;          // m16 tiles per warp
    constexpr int A_ST = BMT * 128;       // bytes per A stage
    constexpr int B_ST = BN * 128;
    constexpr int STG = A_ST + B_ST;
    extern __shared__ char smem[];
    const uint32_t sbase = smem_u32(smem);

    const int tid = threadIdx.x;
    const int wid = tid >> 5;
    const int lane = tid & 31;
    const int g = lane >> 2;              // 0..7
    const int t = lane & 3;               // 0..3
    const int warp_m = wid >> 1;          // 0..1
    const int warp_n = wid & 1;           // 0..1
    const int m0 = blockIdx.y * BMT;
    const int n0 = blockIdx.x * BN;
    const int KT = K / BKH;

    const int lc = tid & 7;               // loader chunk
    const int lr = tid >> 3;              // loader row base (0..15)

    auto load_stage = [&](int stage, int kt) {
        const __half* Ak = A + (size_t)m0 * K + kt * BKH;
        const __half* Bk = BT + (size_t)n0 * K + kt * BKH;
        const uint32_t sA = sbase + stage * STG;
        const uint32_t sB = sA + A_ST;
#pragma unroll
        for (int i = 0; i < BMT / 16; i++) {
            int row = i * 16 + lr;
            cp16(sA + row * 128 + (((lc + ((row & 1) << 2)) & 7) << 4),
                 Ak + (size_t)row * K + lc * 8);
        }
#pragma unroll
        for (int i = 0; i < BN / 16; i++) {
            int row = i * 16 + lr;
            cp16(sB + row * 128 + (((lc + ((row & 1) << 2)) & 7) << 4),
                 Bk + (size_t)row * K + lc * 8);
        }
        cp_commit();
    };

    float acc[MT][8][4];
#pragma unroll
    for (int i = 0; i < MT; i++)
#pragma unroll
        for (int j = 0; j < 8; j++)
#pragma unroll
            for (int r = 0; r < 4; r++) acc[i][j][r] = 0.0f;

    load_stage(0, 0);
    load_stage(1, 1);

    const int gp = g & 1;                 // row parity for all fragment rows

    for (int kt = 0; kt < KT; ++kt) {
        cp_wait<1>();
        __syncthreads();
        if (kt + 2 < KT) load_stage((kt + 2) % STAGES, kt + 2);

        const char* sA = smem + (kt % STAGES) * STG;
        const char* sB = sA + A_ST;

#pragma unroll
        for (int h = 0; h < 2; h++) {
            const int ch = t + ((h ^ gp) << 2);   // swizzled chunk, 0..7
            float4 av[MT][2];
#pragma unroll
            for (int mt = 0; mt < MT; mt++)
#pragma unroll
                for (int rr = 0; rr < 2; rr++) {
                    int row = warp_m * (BMT / 2) + mt * 16 + rr * 8 + g;
                    av[mt][rr] = *(const float4*)(sA + row * 128 + ch * 16);
                }
            float4 bv[8];
#pragma unroll
            for (int nt = 0; nt < 8; nt++) {
                int row = warp_n * 64 + nt * 8 + g;
                bv[nt] = *(const float4*)(sB + row * 128 + ch * 16);
            }
#pragma unroll
            for (int mt = 0; mt < MT; mt++) {
#pragma unroll
                for (int nt = 0; nt < 8; nt++) {
                    mma_f16(acc[mt][nt],
                            F4U(av[mt][0], 0), F4U(av[mt][1], 0),
                            F4U(av[mt][0], 1), F4U(av[mt][1], 1),
                            F4U(bv[nt], 0), F4U(bv[nt], 1));
                    mma_f16(acc[mt][nt],
                            F4U(av[mt][0], 2), F4U(av[mt][1], 2),
                            F4U(av[mt][0], 3), F4U(av[mt][1], 3),
                            F4U(bv[nt], 2), F4U(bv[nt], 3));
                }
            }
        }
    }

    // epilogue: bias in fp32, output fp32 or fp16
#pragma unroll
    for (int mt = 0; mt < MT; mt++) {
        const int r0 = m0 + warp_m * (BMT / 2) + mt * 16 + g;
#pragma unroll
        for (int nt = 0; nt < 8; nt++) {
            const int col = n0 + warp_n * 64 + nt * 8 + 2 * t;
            const float2 bv = *reinterpret_cast<const float2*>(bias + col);
            float2 o0, o1;
            o0.x = acc[mt][nt][0] + bv.x;
            o0.y = acc[mt][nt][1] + bv.y;
            o1.x = acc[mt][nt][2] + bv.x;
            o1.y = acc[mt][nt][3] + bv.y;
            if constexpr (sizeof(OutT) == 4) {
                float* Cf = (float*)C;
                *reinterpret_cast<float2*>(Cf + (size_t)r0 * Ndim + col) = o0;
                *reinterpret_cast<float2*>(Cf + (size_t)(r0 + 8) * Ndim + col) = o1;
            } else {
                __half* Ch = (__half*)C;
                __half2 h0 = __floats2half2_rn(o0.x, o0.y);
                __half2 h1 = __floats2half2_rn(o1.x, o1.y);
                *reinterpret_cast<__half2*>(Ch + (size_t)r0 * Ndim + col) = h0;
                *reinterpret_cast<__half2*>(Ch + (size_t)(r0 + 8) * Ndim + col) = h1;
            }
        }
    }
}

// ---------------- pre-pass kernels (write permuted fp16 layouts) ------------
__global__ __launch_bounds__(256)
void x_to_half_perm(const float* __restrict__ in, __half* __restrict__ out) {
    int q = blockIdx.x * blockDim.x + threadIdx.x;
    if (q >= M_TOT * DIM / 8) return;
    int r = q / (DIM / 8);
    int c = q % (DIM / 8);
    int grp = c >> 2, t = c & 3;
    const float* src = in + (size_t)r * DIM + grp * 32 + 2 * t;
    __half2 h0 = __floats2half2_rn(src[0], src[1]);
    __half2 h1 = __floats2half2_rn(src[8], src[9]);
    __half2 h2 = __floats2half2_rn(src[16], src[17]);
    __half2 h3 = __floats2half2_rn(src[24], src[25]);
    uint4 o;
    o.x = *reinterpret_cast<uint32_t*>(&h0);
    o.y = *reinterpret_cast<uint32_t*>(&h1);
    o.z = *reinterpret_cast<uint32_t*>(&h2);
    o.w = *reinterpret_cast<uint32_t*>(&h3);
    reinterpret_cast<uint4*>(out)[q] = o;
}

// in: R x C row-major fp32; out: C x R halves, chunk-permuted along R(=K)
__global__ __launch_bounds__(1024)
void transpose_half_perm(const float* __restrict__ in, __half* __restrict__ out,
                         int R, int C) {
    __shared__ float tbuf[32][33];
    int c = blockIdx.x * 32 + threadIdx.x;
    int r = blockIdx.y * 32 + threadIdx.y;
    tbuf[threadIdx.y][threadIdx.x] = in[(size_t)r * C + c];
    __syncthreads();
    int oc = blockIdx.y * 32 + threadIdx.x;     // K index
    int orow = blockIdx.x * 32 + threadIdx.y;   // N index
    int w = oc & 31;
    int ppos = (oc & ~31) | (((w >> 1) & 3) << 3) | ((w >> 3) << 1) | (w & 1);
    out[(size_t)orow * R + ppos] = __float2half_rn(tbuf[threadIdx.x][threadIdx.y]);
}

// ---------------- anchor attention (one warp per (b,h,s), fp16 QKV) ---------
__global__ __launch_bounds__(256)
void anchor_attn_kernel(const float* __restrict__ gs) {
    const int gw = (blockIdx.x * blockDim.x + threadIdx.x) >> 5;
    const int lane = threadIdx.x & 31;

    const int s = gw % SS;
    const int h = (gw / SS) % NH;
    const int b = gw / (SS * NH);

    const float g0 = gs[0], g1 = gs[1], g2 = gs[2];
    const float mx = fmaxf(g0, fmaxf(g1, g2));
    const float lse = mx + logf(expf(g0 - mx) + expf(g1 - mx) + expf(g2 - mx));
    const float lw0 = g0 - lse, lw1 = g1 - lse, lw2 = g2 - lse;

    const __half* base = g_qkvh + (size_t)b * SS * N_QKV;
    const int hc = h * HD + lane * 4;

    float4 q;
    {
        const __half2* qp = reinterpret_cast<const __half2*>(
            base + (size_t)s * N_QKV + hc);
        float2 a = __half22float2(qp[0]);
        float2 c = __half22float2(qp[1]);
        q = make_float4(a.x, a.y, c.x, c.y);
    }

    int aidx[SIGMA];
    const int offs[10] = {-3, -2, -1, 1, 2, 3, -10, -5, 5, 10};
#pragma unroll
    for (int a = 0; a < 10; a++) {
        int j = s + offs[a];
        aidx[a] = j < 0 ? 0 : (j > SS - 1 ? SS - 1 : j);
    }
    aidx[10] = 0;
    aidx[11] = SS - 1;

    const float scale = 0.08838834764831845f;
    float sc[SIGMA];
#pragma unroll
    for (int a = 0; a < SIGMA; a++) {
        const __half2* kp = reinterpret_cast<const __half2*>(
            base + (size_t)aidx[a] * N_QKV + DIM + hc);
        float2 k0 = __half22float2(kp[0]);
        float2 k1 = __half22float2(kp[1]);
        float d = q.x * k0.x + q.y * k0.y + q.z * k1.x + q.w * k1.y;
#pragma unroll
        for (int o = 16; o > 0; o >>= 1)
            d += __shfl_xor_sync(0xffffffffu, d, o);
        const float lw = (a < 6) ? lw0 : ((a < 10) ? lw1 : lw2);
        sc[a] = d * scale + lw;
    }

    float m = sc[0];
#pragma unroll
    for (int a = 1; a < SIGMA; a++) m = fmaxf(m, sc[a]);
    float sum = 0.0f;
#pragma unroll
    for (int a = 0; a < SIGMA; a++) { sc[a] = __expf(sc[a] - m); sum += sc[a]; }
    const float inv = 1.0f / sum;

    // permuted-chunk dims this lane owns:
    // chunk c = lane>>1 (within head), halfsel = lane&1
    // dims = G*32 + 16*halfsel + 2t + {0,1,8,9}, G = c>>2, t = c&3
    const int cch = lane >> 1;
    const int hs = lane & 1;
    const int d0 = h * HD + (cch >> 2) * 32 + hs * 16 + 2 * (cch & 3);
    float4 acc = make_float4(0.f, 0.f, 0.f, 0.f);
#pragma unroll
    for (int a = 0; a < SIGMA; a++) {
        const float w = sc[a] * inv;
        const __half* vr = base + (size_t)aidx[a] * N_QKV + 2 * DIM + d0;
        float2 v0 = __half22float2(*reinterpret_cast<const __half2*>(vr));
        float2 v1 = __half22float2(*reinterpret_cast<const __half2*>(vr + 8));
        acc.x += w * v0.x; acc.y += w * v0.y;
        acc.z += w * v1.x; acc.w += w * v1.y;
    }

    __half2 p0 = __floats2half2_rn(acc.x, acc.y);
    __half2 p1 = __floats2half2_rn(acc.z, acc.w);
    uint2 o;
    o.x = *reinterpret_cast<uint32_t*>(&p0);
    o.y = *reinterpret_cast<uint32_t*>(&p1);
    *reinterpret_cast<uint2*>(
        g_att + (size_t)(b * SS + s) * DIM + h * HD + cch * 8 + hs * 4) = o;
}

// ---------------------------------------------------------------------------
extern "C" void kernel_launch(void* const* d_in, const int* in_sizes, int n_in,
                              void* d_out, int out_size) {
    const float* x    = (const float*)d_in[0];
    const float* Wqkv = (const float*)d_in[1];
    const float* bqkv = (const float*)d_in[2];
    const float* Wout = (const float*)d_in[3];
    const float* bout = (const float*)d_in[4];
    const float* gsc  = (const float*)d_in[5];
    float* out = (float*)d_out;

    __half *pxh, *pwqkvT, *pwoutT, *patt, *pqkvh;
    cudaGetSymbolAddress((void**)&pxh, g_xh);
    cudaGetSymbolAddress((void**)&pwqkvT, g_wqkvT);
    cudaGetSymbolAddress((void**)&pwoutT, g_woutT);
    cudaGetSymbolAddress((void**)&pqkvh, g_qkvh);
    cudaGetSymbolAddress((void**)&patt, g_att);

    constexpr int SM128 = STAGES * (128 * 128 + BN * 128);  // 98304
    constexpr int SM64  = STAGES * (64 * 128 + BN * 128);   // 73728

    static bool attr_set = false;
    if (!attr_set) {
        cudaFuncSetAttribute((const void*)gemm_f16_mma<128, __half>,
                             cudaFuncAttributeMaxDynamicSharedMemorySize, SM128);
        cudaFuncSetAttribute((const void*)gemm_f16_mma<64, float>,
                             cudaFuncAttributeMaxDynamicSharedMemorySize, SM64);
        attr_set = true;
    }

    // 1) x -> permuted fp16
    x_to_half_perm<<<(M_TOT * DIM / 8 + 255) / 256, 256>>>(x, pxh);
    // 2) transpose + permute weights -> fp16
    transpose_half_perm<<<dim3(N_QKV / 32, DIM / 32), dim3(32, 32)>>>(Wqkv, pwqkvT, DIM, N_QKV);
    transpose_half_perm<<<dim3(DIM / 32, DIM / 32), dim3(32, 32)>>>(Wout, pwoutT, DIM, DIM);

    // 3) QKV projection: (4096x1536) @ (1536x4608) -> fp16
    gemm_f16_mma<128, __half><<<dim3(N_QKV / BN, M_TOT / 128), 128, SM128>>>(
        pxh, pwqkvT, bqkv, pqkvh, N_QKV, DIM);

    // 4) anchor attention
    anchor_attn_kernel<<<BB * NH * SS * 32 / 256, 256>>>(gsc);

    // 5) output projection: (4096x1536) @ (1536x1536) -> fp32 out
    gemm_f16_mma<64, float><<<dim3(DIM / BN, M_TOT / 64), 128, SM64>>>(
        patt, pwoutT, bout, out, DIM, DIM);
}